// round 4
// baseline (speedup 1.0000x reference)
#include <cuda_runtime.h>
#include <math.h>

#define NB      512
#define NC      10
#define NHW     4096
#define THREADS 256
#define SR_PER_B 128   // 65536 strategic_reasoning elems / 512 blocks

// Per-sample scratch (no allocations allowed)
__device__ float        g_focal[NB];
__device__ int          g_eqcnt[NB];
__device__ unsigned int g_flags[NB];    // bit0 = eq_all, bit1 = copy_all
__device__ int          g_unique[NB];
__device__ unsigned int g_present[NB];  // color presence bitmask
__device__ float        g_cs[NB];       // partial sigmoid sums
__device__ unsigned int g_ticket = 0u;  // reset to 0 by last block each launch

__global__ __launch_bounds__(THREADS)
void fused_kernel(const float* __restrict__ pred,
                  const int*   __restrict__ targets,
                  const int*   __restrict__ inputs,
                  const float* __restrict__ sr,
                  float*       __restrict__ out,
                  int srn)
{
    const int b = blockIdx.x;
    const int t = threadIdx.x;

    __shared__ unsigned char sidx[NHW];      // argmax per pixel
    __shared__ unsigned int  bitmap[320];    // 10240 bits >= 10^4 codes
    __shared__ float         s_f[8];
    __shared__ float         s_cs[8];
    __shared__ int           s_i[8];
    __shared__ int           s_u[8];
    __shared__ unsigned int  s_present;
    __shared__ unsigned int  s_all;
    __shared__ bool          s_last;

    for (int i = t; i < 320; i += THREADS) bitmap[i] = 0u;
    if (t == 0) { s_present = 0u; s_all = 3u; }
    __syncthreads();

    // Creativity partial: this block's 128 contiguous sr elements.
    float cs = 0.f;
    if (t < SR_PER_B) {
        const float v = sr[b * SR_PER_B + t];
        cs = 1.f / (1.f + __expf(-v));
    }

    const float* pb = pred + (size_t)b * NC * NHW;
    const int4*  tb = (const int4*)(targets + (size_t)b * NHW);
    const int4*  ib = (const int4*)(inputs  + (size_t)b * NHW);

    float        focal   = 0.f;
    int          eqcnt   = 0;
    unsigned int flags   = 3u;   // assume all-eq, all-copy until disproven
    unsigned int present = 0u;

    #pragma unroll 1
    for (int iter = 0; iter < 4; iter++) {
        const int g = iter * THREADS + t;        // float4 group; pixels [4g, 4g+3]

        float lv[4][NC];
        #pragma unroll
        for (int c = 0; c < NC; c++) {
            float4 v = ((const float4*)(pb + c * NHW))[g];
            lv[0][c] = v.x; lv[1][c] = v.y; lv[2][c] = v.z; lv[3][c] = v.w;
        }
        const int4 tg4 = tb[g];
        const int4 in4 = ib[g];
        const int tgt[4] = {tg4.x, tg4.y, tg4.z, tg4.w};
        const int inp[4] = {in4.x, in4.y, in4.z, in4.w};

        unsigned int packed = 0u;
        #pragma unroll
        for (int p = 0; p < 4; p++) {
            float m  = lv[p][0];
            float xt = lv[p][0];
            int   am = 0;
            #pragma unroll
            for (int c = 1; c < NC; c++) {
                const float v = lv[p][c];
                xt = (c == tgt[p]) ? v : xt;
                am = (v > m) ? c : am;
                m  = fmaxf(v, m);
            }
            float se = 0.f, et = 0.f;
            #pragma unroll
            for (int c = 0; c < NC; c++) {
                const float e = __expf(lv[p][c] - m);
                se += e;
                et = (c == tgt[p]) ? e : et;
            }
            const float pt = et / se;
            const float ce = __logf(se) - (xt - m);
            const float om = 1.f - pt;
            focal += om * om * ce;

            eqcnt += (am == tgt[p]);
            if (am != tgt[p]) flags &= ~1u;
            if (am != inp[p]) flags &= ~2u;
            present |= 1u << tgt[p];
            packed  |= (unsigned int)am << (8 * p);
        }
        *(unsigned int*)&sidx[g * 4] = packed;
    }

    // Warp-level reduce (fixed shuffle pattern -> deterministic)
    #pragma unroll
    for (int o = 16; o > 0; o >>= 1) {
        focal += __shfl_down_sync(0xffffffffu, focal, o);
        eqcnt += __shfl_down_sync(0xffffffffu, eqcnt, o);
        cs    += __shfl_down_sync(0xffffffffu, cs,    o);
    }
    flags   = __reduce_and_sync(0xffffffffu, flags);
    present = __reduce_or_sync (0xffffffffu, present);

    const int warp = t >> 5, lane = t & 31;
    if (lane == 0) {
        s_f[warp]  = focal;
        s_cs[warp] = cs;
        s_i[warp]  = eqcnt;
        atomicAnd(&s_all, flags);
        atomicOr(&s_present, present);
    }
    __syncthreads();   // sidx + warp partials complete

    // Diversity: 63x63 windows -> base-10 code -> presence bitmap
    for (int i = t; i < 63 * 63; i += THREADS) {
        const int r  = i / 63, c0 = i % 63;
        const int a  = sidx[r * 64 + c0];
        const int bb = sidx[r * 64 + c0 + 1];
        const int cc = sidx[r * 64 + 64 + c0];
        const int dd = sidx[r * 64 + 64 + c0 + 1];
        const int code = a * 1000 + bb * 100 + cc * 10 + dd;
        atomicOr(&bitmap[code >> 5], 1u << (code & 31));
    }
    __syncthreads();

    int u = 0;
    for (int i = t; i < 320; i += THREADS) u += __popc(bitmap[i]);
    #pragma unroll
    for (int o = 16; o > 0; o >>= 1) u += __shfl_down_sync(0xffffffffu, u, o);
    if (lane == 0) s_u[warp] = u;
    __syncthreads();

    if (t == 0) {
        float fs = 0.f, css = 0.f; int ec = 0, uu = 0;
        #pragma unroll
        for (int w = 0; w < 8; w++) {
            fs += s_f[w]; css += s_cs[w]; ec += s_i[w]; uu += s_u[w];
        }
        g_focal[b]   = fs;
        g_cs[b]      = css;
        g_eqcnt[b]   = ec;
        g_unique[b]  = uu;
        g_flags[b]   = s_all;
        g_present[b] = s_present;
        __threadfence();                       // publish record before ticket
        const unsigned int tk = atomicAdd(&g_ticket, 1u);
        s_last = (tk == NB - 1);
    }
    __syncthreads();

    if (!s_last) return;

    // ---- Last block: fold 512 per-sample records into the 10 outputs ----
    __threadfence();   // order record reads after ticket observation
    __shared__ float red[8][6];

    float a_cs = 0.f, a_fo = 0.f, a_iou = 0.f, a_comb = 0.f, a_cpy = 0.f, a_dv = 0.f;
    #pragma unroll
    for (int k = 0; k < 2; k++) {
        const int s = k * THREADS + t;
        const unsigned int pres  = __ldcg(&g_present[s]);
        const unsigned int fl    = __ldcg(&g_flags[s]);
        const float        fsum  = __ldcg(&g_focal[s]);
        const float        csum  = __ldcg(&g_cs[s]);
        const int          ec    = __ldcg(&g_eqcnt[s]);
        const int          uu    = __ldcg(&g_unique[s]);

        const float w   = (__popc(pres) > 3) ? 1.2f : 1.0f;
        const float iou = (float)ec * (1.f / (float)NHW);
        const float st  = (fl & 1u) ? 1.f : 0.f;
        a_fo   += fsum * w;
        a_cs   += csum;
        a_iou  += iou;
        a_comb += 0.2f * st + 0.8f * iou;
        a_cpy  += (fl & 2u) ? 1.f : 0.f;
        a_dv   += (float)uu * (1.f / 3969.f);
    }

    #pragma unroll
    for (int o = 16; o > 0; o >>= 1) {
        a_cs   += __shfl_down_sync(0xffffffffu, a_cs,   o);
        a_fo   += __shfl_down_sync(0xffffffffu, a_fo,   o);
        a_iou  += __shfl_down_sync(0xffffffffu, a_iou,  o);
        a_comb += __shfl_down_sync(0xffffffffu, a_comb, o);
        a_cpy  += __shfl_down_sync(0xffffffffu, a_cpy,  o);
        a_dv   += __shfl_down_sync(0xffffffffu, a_dv,   o);
    }
    if (lane == 0) {
        red[warp][0] = a_cs;  red[warp][1] = a_fo;  red[warp][2] = a_iou;
        red[warp][3] = a_comb; red[warp][4] = a_cpy; red[warp][5] = a_dv;
    }
    __syncthreads();

    if (t == 0) {
        float S[6] = {0.f, 0.f, 0.f, 0.f, 0.f, 0.f};
        #pragma unroll
        for (int wq = 0; wq < 8; wq++)
            #pragma unroll
            for (int q = 0; q < 6; q++) S[q] += red[wq][q];

        const float cs_sum = S[0], focal_sum = S[1], iou_sum = S[2];
        const float comb_sum = S[3], copy_sum = S[4], uniq_sum = S[5];

        const float focal_loss   = focal_sum / ((float)NB * (float)NHW);
        const float transform    = (copy_sum / (float)NB) * 0.2f;
        const float comb_mean    = comb_sum / (float)NB;
        const float exact_bonus  = fmaxf(-comb_mean * 5.0f, -3.0f);
        const float iou_mean     = iou_sum / (float)NB;
        const float creativity   = (cs_sum / (float)srn) * 0.15f;
        const float diversity    = (uniq_sum / (float)NB) * 0.02f;
        const float grid_factor  = fminf((float)NHW / 900.0f, 1.0f);
        const float grid_bonus   = comb_mean * grid_factor * 0.05f;

        float total = focal_loss + transform + exact_bonus
                    - creativity - diversity - grid_bonus;
        if (isnan(total) || isinf(total)) total = fminf(focal_loss, 10.0f);

        out[0] = total;
        out[1] = focal_loss;
        out[2] = transform;
        out[3] = exact_bonus;
        out[4] = comb_sum;
        out[5] = comb_sum;
        out[6] = iou_mean;
        out[7] = creativity;
        out[8] = diversity;
        out[9] = grid_bonus;

        g_ticket = 0u;     // restore for next graph replay (deterministic)
    }
}

extern "C" void kernel_launch(void* const* d_in, const int* in_sizes, int n_in,
                              void* d_out, int out_size)
{
    const float* pred    = (const float*)d_in[0];
    const int*   targets = (const int*)d_in[1];
    const int*   inputs  = (const int*)d_in[2];
    const float* sr      = (const float*)d_in[3];

    fused_kernel<<<NB, THREADS>>>(pred, targets, inputs, sr,
                                  (float*)d_out, in_sizes[3]);
}

// round 5
// speedup vs baseline: 1.0703x; 1.0703x over previous
#include <cuda_runtime.h>
#include <math.h>

#define NB      512
#define NC      10
#define NHW     4096
#define THREADS 256
#define SR_PER_B 128   // 65536 strategic_reasoning elems / 512 blocks

// Per-sample scratch (no allocations allowed)
__device__ float        g_focal[NB];
__device__ int          g_eqcnt[NB];
__device__ unsigned int g_flags[NB];    // bit0 = eq_all, bit1 = copy_all
__device__ int          g_unique[NB];
__device__ unsigned int g_present[NB];  // color presence bitmask
__device__ float        g_cs[NB];       // partial sigmoid sums
__device__ unsigned int g_ticket = 0u;  // reset to 0 by last block each launch

__global__ __launch_bounds__(THREADS, 4)   // cap regs at 64 -> 4 blocks/SM -> single wave
void fused_kernel(const float* __restrict__ pred,
                  const int*   __restrict__ targets,
                  const int*   __restrict__ inputs,
                  const float* __restrict__ sr,
                  float*       __restrict__ out,
                  int srn)
{
    const int b = blockIdx.x;
    const int t = threadIdx.x;

    __shared__ unsigned char sidx[NHW];      // argmax per pixel
    __shared__ unsigned int  bitmap[320];    // 10240 bits >= 10^4 codes
    __shared__ float         s_f[8];
    __shared__ float         s_cs[8];
    __shared__ int           s_i[8];
    __shared__ int           s_u[8];
    __shared__ unsigned int  s_present;
    __shared__ unsigned int  s_all;
    __shared__ bool          s_last;

    for (int i = t; i < 320; i += THREADS) bitmap[i] = 0u;
    if (t == 0) { s_present = 0u; s_all = 3u; }
    __syncthreads();

    // Creativity partial: this block's 128 contiguous sr elements.
    float cs = 0.f;
    if (t < SR_PER_B) {
        const float v = sr[b * SR_PER_B + t];
        cs = 1.f / (1.f + __expf(-v));
    }

    const float* pb = pred + (size_t)b * NC * NHW;
    const int2*  tb = (const int2*)(targets + (size_t)b * NHW);
    const int2*  ib = (const int2*)(inputs  + (size_t)b * NHW);

    float        focal   = 0.f;
    int          eqcnt   = 0;
    unsigned int flags   = 3u;   // assume all-eq, all-copy until disproven
    unsigned int present = 0u;

    #pragma unroll 1
    for (int iter = 0; iter < 8; iter++) {
        const int g = iter * THREADS + t;        // float2 group; pixels 2g, 2g+1

        float lv[2][NC];
        #pragma unroll
        for (int c = 0; c < NC; c++) {
            const float2 v = ((const float2*)(pb + c * NHW))[g];
            lv[0][c] = v.x; lv[1][c] = v.y;
        }
        const int2 tg2 = tb[g];
        const int2 in2 = ib[g];
        const int tgt[2] = {tg2.x, tg2.y};
        const int inp[2] = {in2.x, in2.y};

        unsigned int packed = 0u;
        #pragma unroll
        for (int p = 0; p < 2; p++) {
            float m  = lv[p][0];
            float xt = lv[p][0];
            int   am = 0;
            #pragma unroll
            for (int c = 1; c < NC; c++) {
                const float v = lv[p][c];
                xt = (c == tgt[p]) ? v : xt;
                am = (v > m) ? c : am;
                m  = fmaxf(v, m);
            }
            float se = 0.f;
            #pragma unroll
            for (int c = 0; c < NC; c++)
                se += __expf(lv[p][c] - m);

            const float d  = xt - m;            // <= 0
            const float et = __expf(d);
            const float pt = et / se;
            const float ce = __logf(se) - d;
            const float om = 1.f - pt;
            focal += om * om * ce;

            eqcnt += (am == tgt[p]);
            if (am != tgt[p]) flags &= ~1u;
            if (am != inp[p]) flags &= ~2u;
            present |= 1u << tgt[p];
            packed  |= (unsigned int)am << (8 * p);
        }
        ((unsigned short*)sidx)[g] = (unsigned short)packed;
    }

    // Warp-level reduce (fixed shuffle pattern -> deterministic)
    #pragma unroll
    for (int o = 16; o > 0; o >>= 1) {
        focal += __shfl_down_sync(0xffffffffu, focal, o);
        eqcnt += __shfl_down_sync(0xffffffffu, eqcnt, o);
        cs    += __shfl_down_sync(0xffffffffu, cs,    o);
    }
    flags   = __reduce_and_sync(0xffffffffu, flags);
    present = __reduce_or_sync (0xffffffffu, present);

    const int warp = t >> 5, lane = t & 31;
    if (lane == 0) {
        s_f[warp]  = focal;
        s_cs[warp] = cs;
        s_i[warp]  = eqcnt;
        atomicAnd(&s_all, flags);
        atomicOr(&s_present, present);
    }
    __syncthreads();   // sidx + warp partials complete

    // Diversity: 63x63 windows -> base-10 code -> presence bitmap
    for (int i = t; i < 63 * 63; i += THREADS) {
        const int r  = i / 63, c0 = i % 63;
        const int a  = sidx[r * 64 + c0];
        const int bb = sidx[r * 64 + c0 + 1];
        const int cc = sidx[r * 64 + 64 + c0];
        const int dd = sidx[r * 64 + 64 + c0 + 1];
        const int code = a * 1000 + bb * 100 + cc * 10 + dd;
        atomicOr(&bitmap[code >> 5], 1u << (code & 31));
    }
    __syncthreads();

    int u = 0;
    for (int i = t; i < 320; i += THREADS) u += __popc(bitmap[i]);
    #pragma unroll
    for (int o = 16; o > 0; o >>= 1) u += __shfl_down_sync(0xffffffffu, u, o);
    if (lane == 0) s_u[warp] = u;
    __syncthreads();

    if (t == 0) {
        float fs = 0.f, css = 0.f; int ec = 0, uu = 0;
        #pragma unroll
        for (int w = 0; w < 8; w++) {
            fs += s_f[w]; css += s_cs[w]; ec += s_i[w]; uu += s_u[w];
        }
        g_focal[b]   = fs;
        g_cs[b]      = css;
        g_eqcnt[b]   = ec;
        g_unique[b]  = uu;
        g_flags[b]   = s_all;
        g_present[b] = s_present;
        __threadfence();                       // publish record before ticket
        const unsigned int tk = atomicAdd(&g_ticket, 1u);
        s_last = (tk == NB - 1);
    }
    __syncthreads();

    if (!s_last) return;

    // ---- Last block: fold 512 per-sample records into the 10 outputs ----
    __threadfence();   // order record reads after ticket observation
    __shared__ float red[8][6];

    float a_cs = 0.f, a_fo = 0.f, a_iou = 0.f, a_comb = 0.f, a_cpy = 0.f, a_dv = 0.f;
    #pragma unroll
    for (int k = 0; k < 2; k++) {
        const int s = k * THREADS + t;
        const unsigned int pres  = __ldcg(&g_present[s]);
        const unsigned int fl    = __ldcg(&g_flags[s]);
        const float        fsum  = __ldcg(&g_focal[s]);
        const float        csum  = __ldcg(&g_cs[s]);
        const int          ec    = __ldcg(&g_eqcnt[s]);
        const int          uu    = __ldcg(&g_unique[s]);

        const float w   = (__popc(pres) > 3) ? 1.2f : 1.0f;
        const float iou = (float)ec * (1.f / (float)NHW);
        const float st  = (fl & 1u) ? 1.f : 0.f;
        a_fo   += fsum * w;
        a_cs   += csum;
        a_iou  += iou;
        a_comb += 0.2f * st + 0.8f * iou;
        a_cpy  += (fl & 2u) ? 1.f : 0.f;
        a_dv   += (float)uu * (1.f / 3969.f);
    }

    #pragma unroll
    for (int o = 16; o > 0; o >>= 1) {
        a_cs   += __shfl_down_sync(0xffffffffu, a_cs,   o);
        a_fo   += __shfl_down_sync(0xffffffffu, a_fo,   o);
        a_iou  += __shfl_down_sync(0xffffffffu, a_iou,  o);
        a_comb += __shfl_down_sync(0xffffffffu, a_comb, o);
        a_cpy  += __shfl_down_sync(0xffffffffu, a_cpy,  o);
        a_dv   += __shfl_down_sync(0xffffffffu, a_dv,   o);
    }
    if (lane == 0) {
        red[warp][0] = a_cs;  red[warp][1] = a_fo;  red[warp][2] = a_iou;
        red[warp][3] = a_comb; red[warp][4] = a_cpy; red[warp][5] = a_dv;
    }
    __syncthreads();

    if (t == 0) {
        float S[6] = {0.f, 0.f, 0.f, 0.f, 0.f, 0.f};
        #pragma unroll
        for (int wq = 0; wq < 8; wq++)
            #pragma unroll
            for (int q = 0; q < 6; q++) S[q] += red[wq][q];

        const float cs_sum = S[0], focal_sum = S[1], iou_sum = S[2];
        const float comb_sum = S[3], copy_sum = S[4], uniq_sum = S[5];

        const float focal_loss   = focal_sum / ((float)NB * (float)NHW);
        const float transform    = (copy_sum / (float)NB) * 0.2f;
        const float comb_mean    = comb_sum / (float)NB;
        const float exact_bonus  = fmaxf(-comb_mean * 5.0f, -3.0f);
        const float iou_mean     = iou_sum / (float)NB;
        const float creativity   = (cs_sum / (float)srn) * 0.15f;
        const float diversity    = (uniq_sum / (float)NB) * 0.02f;
        const float grid_factor  = fminf((float)NHW / 900.0f, 1.0f);
        const float grid_bonus   = comb_mean * grid_factor * 0.05f;

        float total = focal_loss + transform + exact_bonus
                    - creativity - diversity - grid_bonus;
        if (isnan(total) || isinf(total)) total = fminf(focal_loss, 10.0f);

        out[0] = total;
        out[1] = focal_loss;
        out[2] = transform;
        out[3] = exact_bonus;
        out[4] = comb_sum;
        out[5] = comb_sum;
        out[6] = iou_mean;
        out[7] = creativity;
        out[8] = diversity;
        out[9] = grid_bonus;

        g_ticket = 0u;     // restore for next graph replay (deterministic)
    }
}

extern "C" void kernel_launch(void* const* d_in, const int* in_sizes, int n_in,
                              void* d_out, int out_size)
{
    const float* pred    = (const float*)d_in[0];
    const int*   targets = (const int*)d_in[1];
    const int*   inputs  = (const int*)d_in[2];
    const float* sr      = (const float*)d_in[3];

    fused_kernel<<<NB, THREADS>>>(pred, targets, inputs, sr,
                                  (float*)d_out, in_sizes[3]);
}